// round 4
// baseline (speedup 1.0000x reference)
#include <cuda_runtime.h>

#define B_    256
#define V_    128000
#define P_    512
#define O_    128
#define NT    512
#define NWARP 16
#define HB    2048
#define HMASK (HB-1)
#define NBIN  4096
#define SCAP  2048
#define RCAP  1024
#define NCH   (V_/4)
#define NEG_INF (__int_as_float(0xff800000))
#define TINYF 1.1754943508222875e-38f
#define EPS_T 1e-5f

// output layout (floats): [sampled B][idx B*21][lp B*21][ranks B]
#define IDX_OFF 256
#define LP_OFF  5632
#define RK_OFF  11008

// shared memory byte offsets
#define SM_U1 0          // bitmap int[4096]  -> later ssort_val f[2048] @0, ssort_idx i[2048] @8192
#define SM_U2 16384      // hkey i[2048] @16384, haux i[2048] @24576 -> later rsort_val f[1024] @16384, rsort_idx i[1024] @20480
#define SM_H  32768      // histS i[4096] @32768, histR i[4096] @49152
                         // -> later s_val f[2048] @32768, s_idx i[2048] @40960, r_val f[1024] @49152, r_idx i[1024] @53248
#define SM_MISC 65536
#define SMEM_TOTAL (65536 + 4096)

struct MiscT {
    int   suf[NT];
    float redf[NWARP];
    float redf2[NWARP];
    int   redi[NWARP];
    float m, logS, tsafe, kth_s, thresh, lp_samp;
    int   Ts, Tr, nsCnt, nrCnt, greedy, chunkSel, keepN, sampled;
};

// order-preserving float -> 12-bit bucket
__device__ __forceinline__ int binOf(float f) {
    unsigned u = __float_as_uint(f);
    u = (u & 0x80000000u) ? ~u : (u | 0x80000000u);
    return (int)(u >> 20);
}

// JAX threefry2x32 partitionable: key=(0,42), counter=(0, idx), bits=x0^x1
__device__ __forceinline__ float gumbel_at(unsigned idx) {
    const unsigned ks0 = 0u, ks1 = 42u, ks2 = 0x1BD11BDAu ^ 42u;
    unsigned x0 = ks0;
    unsigned x1 = idx + ks1;
#define TF_QR(r) { x0 += x1; x1 = (x1 << (r)) | (x1 >> (32 - (r))); x1 ^= x0; }
    TF_QR(13) TF_QR(15) TF_QR(26) TF_QR(6)   x0 += ks1; x1 += ks2 + 1u;
    TF_QR(17) TF_QR(29) TF_QR(16) TF_QR(24)  x0 += ks2; x1 += ks0 + 2u;
    TF_QR(13) TF_QR(15) TF_QR(26) TF_QR(6)   x0 += ks0; x1 += ks1 + 3u;
    TF_QR(17) TF_QR(29) TF_QR(16) TF_QR(24)  x0 += ks1; x1 += ks2 + 4u;
    TF_QR(13) TF_QR(15) TF_QR(26) TF_QR(6)   x0 += ks2; x1 += ks0 + 5u;
#undef TF_QR
    unsigned bits = x0 ^ x1;
    float f = __uint_as_float((bits >> 9) | 0x3F800000u) - 1.0f;
    float u = fmaxf(f + TINYF, TINYF);
    return -logf(-logf(u));
}

__device__ __forceinline__ unsigned hhash(int v) {
    return (((unsigned)v * 2654435761u) >> 21) & HMASK;
}

__device__ __forceinline__ int hinsert(int* hkey, int v) {
    unsigned h = hhash(v);
    while (true) {
        int k = hkey[h];
        if (k == v) return (int)h;
        if (k == -1) {
            int old = atomicCAS(&hkey[h], -1, v);
            if (old == -1 || old == v) return (int)h;
        }
        h = (h + 1) & HMASK;
    }
}

__device__ __forceinline__ int hfind(const int* hkey, int v) {
    unsigned h = hhash(v);
    while (true) {
        int k = hkey[h];
        if (k == v) return (int)h;
        if (k == -1) return -1;
        h = (h + 1) & HMASK;
    }
}

// penalty adjustment, matching reference fp order
__device__ __forceinline__ float adjv(float lg, int aux, float rp, float fq, float pp) {
    int cnt = aux & 0xFFFF;
    bool outseen = cnt > 0;
    bool seen = outseen || (aux & 0x10000);
    float y = lg;
    if (seen) y = (lg > 0.0f) ? (lg / rp) : (lg * rp);
    y = y - fq * (float)cnt;
    y = y - (outseen ? pp : 0.0f);
    return y;
}

// block argmax: (val desc, idx asc). uniform call.
__device__ void blk_argmax(float v, int idx, MiscT* ms, int tid, float* ov, int* oidx) {
#pragma unroll
    for (int off = 16; off; off >>= 1) {
        float v2 = __shfl_down_sync(0xffffffffu, v, off);
        int   i2 = __shfl_down_sync(0xffffffffu, idx, off);
        if (v2 > v || (v2 == v && i2 < idx)) { v = v2; idx = i2; }
    }
    if ((tid & 31) == 0) { ms->redf[tid >> 5] = v; ms->redi[tid >> 5] = idx; }
    __syncthreads();
    if (tid < 32) {
        v = (tid < NWARP) ? ms->redf[tid] : NEG_INF;
        idx = (tid < NWARP) ? ms->redi[tid] : 0x7fffffff;
#pragma unroll
        for (int off = 16; off; off >>= 1) {
            float v2 = __shfl_down_sync(0xffffffffu, v, off);
            int   i2 = __shfl_down_sync(0xffffffffu, idx, off);
            if (v2 > v || (v2 == v && i2 < idx)) { v = v2; idx = i2; }
        }
        if (tid == 0) { ms->redf[0] = v; ms->redi[0] = idx; }
    }
    __syncthreads();
    *ov = ms->redf[0]; *oidx = ms->redi[0];
    __syncthreads();
}

__device__ int blk_isum(int v, MiscT* ms, int tid) {
#pragma unroll
    for (int off = 16; off; off >>= 1) v += __shfl_down_sync(0xffffffffu, v, off);
    if ((tid & 31) == 0) ms->redi[tid >> 5] = v;
    __syncthreads();
    if (tid < 32) {
        v = (tid < NWARP) ? ms->redi[tid] : 0;
#pragma unroll
        for (int off = 16; off; off >>= 1) v += __shfl_down_sync(0xffffffffu, v, off);
        if (tid == 0) ms->redi[0] = v;
    }
    __syncthreads();
    int r = ms->redi[0];
    __syncthreads();
    return r;
}

// histogram top-tail cutoff: largest bin T with count(bins >= T) >= need
__device__ void cutoff_scan(const int* hist, int need, MiscT* ms, int tid, int* outT) {
    int part = 0;
    int b0 = tid * 8;
#pragma unroll
    for (int b = 0; b < 8; b++) part += hist[b0 + b];
    ms->suf[tid] = part;
    __syncthreads();
    for (int off = 1; off < NT; off <<= 1) {
        int v = (tid + off < NT) ? ms->suf[tid + off] : 0;
        __syncthreads();
        ms->suf[tid] += v;
        __syncthreads();
    }
    if (ms->suf[tid] >= need && (tid == NT - 1 || ms->suf[tid + 1] < need))
        ms->chunkSel = tid;
    __syncthreads();
    if (tid == 0) {
        int c = ms->chunkSel;
        int acc = (c < NT - 1) ? ms->suf[c + 1] : 0;
        int T = c * 8;
        for (int b = c * 8 + 7; b >= c * 8; b--) {
            acc += hist[b];
            if (acc >= need) { T = b; break; }
        }
        *outT = T;
    }
    __syncthreads();
}

__global__ __launch_bounds__(NT, 2)
void sampler_kernel(const float* __restrict__ logits,
                    const float* __restrict__ temperature,
                    const float* __restrict__ top_p,
                    const float* __restrict__ freqp,
                    const float* __restrict__ presp,
                    const float* __restrict__ repp,
                    const int*   __restrict__ topk,
                    const int*   __restrict__ ptoks,
                    const int*   __restrict__ otoks,
                    float*       __restrict__ out) {
    extern __shared__ unsigned char sm[];
    int* bitmap = (int*)(sm + SM_U1);          // 4096 ints (uses 4000)
    int* hkey   = (int*)(sm + SM_U2);          // 2048
    int* haux   = (int*)(sm + SM_U2 + 8192);   // 2048
    int* histS  = (int*)(sm + SM_H);           // 4096
    int* histR  = (int*)(sm + SM_H + 16384);   // 4096
    MiscT* ms   = (MiscT*)(sm + SM_MISC);

    const int tid = threadIdx.x;
    const int r = blockIdx.x;
    const float* row = logits + (size_t)r * V_;
    const float4* row4 = (const float4*)row;

    const float tr  = temperature[r];
    const float tpv = top_p[r];
    const float fq  = freqp[r];
    const float pp  = presp[r];
    const float rp  = repp[r];
    int k = topk[r];
    if (k < 1) k = 1; if (k > V_) k = V_;
    const float tsafe = (tr < EPS_T) ? 1.0f : tr;

    // ---- init shared ----
    for (int i = tid; i < 4096; i += NT) { bitmap[i] = 0; histS[i] = 0; histR[i] = 0; }
    for (int i = tid; i < HB; i += NT) { hkey[i] = -1; haux[i] = 0; }
    if (tid == 0) { ms->nsCnt = 0; ms->nrCnt = 0; }
    __syncthreads();

    // ---- build penalty structures ----
    for (int t = tid; t < O_; t += NT) {
        int v = otoks[r * O_ + t];
        atomicOr(&bitmap[v >> 5], 1 << (v & 31));
        int slot = hinsert(hkey, v);
        atomicAdd(&haux[slot], 1);
    }
    for (int t = tid; t < P_; t += NT) {
        int v = ptoks[r * P_ + t];
        atomicOr(&bitmap[v >> 5], 1 << (v & 31));
        int slot = hinsert(hkey, v);
        atomicOr(&haux[slot], 1 << 16);
    }
    __syncthreads();

    // ---- pass 1: stats + histograms ----
    float mloc = NEG_INF, sloc = 0.0f;
    float gbest = NEG_INF; int gidx = 0x7fffffff;
    for (int i = tid; i < NCH; i += NT) {
        float4 L = row4[i];
        int v0 = 4 * i;
        int bits = (bitmap[v0 >> 5] >> (v0 & 31)) & 0xF;
#pragma unroll
        for (int j = 0; j < 4; j++) {
            float lg = (&L.x)[j];
            int v = v0 + j;
            // online logsumexp (raw)
            if (lg > mloc) { sloc = sloc * expf(mloc - lg) + 1.0f; mloc = lg; }
            else sloc += expf(lg - mloc);
            float x = lg;
            if (bits & (1 << j)) {
                int slot = hfind(hkey, v);
                if (slot >= 0) x = adjv(lg, haux[slot], rp, fq, pp);
            }
            if (x > gbest) { gbest = x; gidx = v; }
            atomicAdd(&histS[binOf(x)], 1);
            atomicAdd(&histR[binOf(lg)], 1);
        }
    }
    // reduce logsumexp
    {
#pragma unroll
        for (int off = 16; off; off >>= 1) {
            float m2 = __shfl_down_sync(0xffffffffu, mloc, off);
            float s2 = __shfl_down_sync(0xffffffffu, sloc, off);
            float nm = fmaxf(mloc, m2);
            sloc = sloc * expf(mloc - nm) + s2 * expf(m2 - nm);
            mloc = nm;
        }
        if ((tid & 31) == 0) { ms->redf[tid >> 5] = mloc; ms->redf2[tid >> 5] = sloc; }
        __syncthreads();
        if (tid < 32) {
            float mm = (tid < NWARP) ? ms->redf[tid] : NEG_INF;
            float ss = (tid < NWARP) ? ms->redf2[tid] : 0.0f;
#pragma unroll
            for (int off = 16; off; off >>= 1) {
                float m2 = __shfl_down_sync(0xffffffffu, mm, off);
                float s2 = __shfl_down_sync(0xffffffffu, ss, off);
                float nm = fmaxf(mm, m2);
                ss = ss * expf(mm - nm) + s2 * expf(m2 - nm);
                mm = nm;
            }
            if (tid == 0) { ms->m = mm; ms->logS = logf(ss); }
        }
        __syncthreads();
    }
    // greedy argmax (adjusted)
    {
        float gv; int gi;
        blk_argmax(gbest, gidx, ms, tid, &gv, &gi);
        if (tid == 0) ms->greedy = gi;
        __syncthreads();
    }
    const float m = ms->m, logS = ms->logS;

    // ---- cutoffs from histograms ----
    cutoff_scan(histS, k, ms, tid, &ms->Ts);
    cutoff_scan(histR, 20, ms, tid, &ms->Tr);
    const int Ts = ms->Ts, Tr = ms->Tr;
    __syncthreads();   // hist regions free after this

    float* s_val = (float*)(sm + SM_H);
    int*   s_idx = (int*)(sm + SM_H + 8192);
    float* r_val = (float*)(sm + SM_H + 16384);
    int*   r_idx = (int*)(sm + SM_H + 20480);

    // ---- pass 2: candidate collection ----
    for (int i = tid; i < NCH; i += NT) {
        float4 L = row4[i];
        int v0 = 4 * i;
        int bits = (bitmap[v0 >> 5] >> (v0 & 31)) & 0xF;
#pragma unroll
        for (int j = 0; j < 4; j++) {
            float lg = (&L.x)[j];
            int v = v0 + j;
            float x = lg;
            if (bits & (1 << j)) {
                int slot = hfind(hkey, v);
                if (slot >= 0) x = adjv(lg, haux[slot], rp, fq, pp);
            }
            if (binOf(x) >= Ts) {
                int p = atomicAdd(&ms->nsCnt, 1);
                if (p < SCAP) { s_val[p] = x; s_idx[p] = v; }
            }
            if (binOf(lg) >= Tr) {
                int p = atomicAdd(&ms->nrCnt, 1);
                if (p < RCAP) { r_val[p] = lg; r_idx[p] = v; }
            }
        }
    }
    __syncthreads();
    int ns = ms->nsCnt; if (ns > SCAP) ns = SCAP;
    int nr = ms->nrCnt; if (nr > RCAP) nr = RCAP;
    __syncthreads();   // bitmap/hash free after here

    float* ssort_val = (float*)(sm + SM_U1);
    int*   ssort_idx = (int*)(sm + SM_U1 + 8192);
    float* rsort_val = (float*)(sm + SM_U2);
    int*   rsort_idx = (int*)(sm + SM_U2 + 4096);

    // ---- rank sort (val desc, token idx asc) ----
    for (int i = tid; i < ns; i += NT) {
        float v = s_val[i]; int id = s_idx[i]; int rk = 0;
        for (int j = 0; j < ns; j++) {
            float w = s_val[j];
            rk += (w > v) || (w == v && s_idx[j] < id);
        }
        ssort_val[rk] = v; ssort_idx[rk] = id;
    }
    for (int i = tid; i < nr; i += NT) {
        float v = r_val[i]; int id = r_idx[i]; int rk = 0;
        for (int j = 0; j < nr; j++) {
            float w = r_val[j];
            rk += (w > v) || (w == v && r_idx[j] < id);
        }
        rsort_val[rk] = v; rsort_idx[rk] = id;
    }
    __syncthreads();

    // ---- top-k / top-p / threshold (thread 0, small N) ----
    if (tid == 0) {
        int kk = (k <= ns) ? k : ns;
        float kth_s = ssort_val[kk - 1] / tsafe;
        int keepN = kk;
        while (keepN < ns && (ssort_val[keepN] / tsafe) >= kth_s) keepN++;
        // softmax over kept set (sorted desc), exclusive-cumsum keep rule
        float s0 = ssort_val[0] / tsafe;
        float S = 0.0f;
        for (int i = 0; i < keepN; i++) S += expf(ssort_val[i] / tsafe - s0);
        float cum = 0.0f; int j = 0;
        for (int i = 0; i < keepN; i++) {
            float p = expf(ssort_val[i] / tsafe - s0) / S;
            if (cum < tpv) j++;
            cum += p;
        }
        if (cum < tpv) j += (V_ - keepN);   // tail positions (prob 0) all keep
        int nkeep = (j < 1) ? 1 : j;
        float pth = (nkeep <= keepN) ? (ssort_val[nkeep - 1] / tsafe) : NEG_INF;
        ms->kth_s = kth_s;
        ms->thresh = fmaxf(kth_s, pth);
        ms->keepN = keepN;
    }
    __syncthreads();
    const float thresh = ms->thresh;
    const int keepN = ms->keepN;

    // ---- gumbel argmax over surviving candidates ----
    {
        float bv = NEG_INF; int bidx = 0x7fffffff;
        for (int i = tid; i < keepN; i += NT) {
            float s = ssort_val[i] / tsafe;
            if (s >= thresh) {
                float g = gumbel_at((unsigned)(r * V_) + (unsigned)ssort_idx[i]);
                float val = s + g;
                if (val > bv || (val == bv && ssort_idx[i] < bidx)) { bv = val; bidx = ssort_idx[i]; }
            }
        }
        float rv; int ri;
        blk_argmax(bv, bidx, ms, tid, &rv, &ri);
        if (tid == 0) {
            int sampled = (tr < EPS_T) ? ms->greedy : ri;
            ms->sampled = sampled;
            float lgs = logits[(size_t)r * V_ + sampled];
            ms->lp_samp = (lgs - m) - logS;
        }
        __syncthreads();
    }
    const int sampled = ms->sampled;
    const float lp_samp = ms->lp_samp;

    // ---- outputs (except rank) ----
    if (tid < 20) {
        out[IDX_OFF + r * 21 + tid] = (float)rsort_idx[tid];
        out[LP_OFF  + r * 21 + tid] = (rsort_val[tid] - m) - logS;
    }
    if (tid == 0) {
        out[r] = (float)sampled;
        out[IDX_OFF + r * 21 + 20] = (float)sampled;
        out[LP_OFF  + r * 21 + 20] = lp_samp;
    }

    // ---- pass 3: rank ----
    int cnt = 0;
    for (int i = tid; i < NCH; i += NT) {
        float4 L = row4[i];
#pragma unroll
        for (int j = 0; j < 4; j++) {
            float lg = (&L.x)[j];
            cnt += (((lg - m) - logS) >= lp_samp) ? 1 : 0;
        }
    }
    int total = blk_isum(cnt, ms, tid);
    if (tid == 0) out[RK_OFF + r] = (float)total;
}

extern "C" void kernel_launch(void* const* d_in, const int* in_sizes, int n_in,
                              void* d_out, int out_size) {
    const float* logits = (const float*)d_in[0];
    const float* temperature = (const float*)d_in[1];
    const float* topp = (const float*)d_in[2];
    const float* freqp = (const float*)d_in[3];
    const float* presp = (const float*)d_in[4];
    const float* repp = (const float*)d_in[5];
    const int* topk = (const int*)d_in[6];
    const int* ptoks = (const int*)d_in[7];
    const int* otoks = (const int*)d_in[8];
    float* out = (float*)d_out;

    cudaFuncSetAttribute(sampler_kernel,
                         cudaFuncAttributeMaxDynamicSharedMemorySize, SMEM_TOTAL);
    sampler_kernel<<<B_, NT, SMEM_TOTAL>>>(logits, temperature, topp, freqp,
                                           presp, repp, topk, ptoks, otoks, out);
}

// round 6
// speedup vs baseline: 1.3119x; 1.3119x over previous
#include <cuda_runtime.h>

#define B_    256
#define V_    128000
#define P_    512
#define O_    128
#define NT    512
#define NWARP 16
#define HB    2048
#define HMASK (HB-1)
#define NBIN  4096
#define SCAP  2048
#define RCAP  1024
#define NCH   (V_/4)
#define NEG_INF (__int_as_float(0xff800000))
#define TINYF 1.1754943508222875e-38f
#define EPS_T 1e-5f

// output layout (floats): [sampled B][idx B*21][lp B*21][ranks B]
#define IDX_OFF 256
#define LP_OFF  5632
#define RK_OFF  11008

// ---- shared memory layout (byte offsets) ----
// phase A (build/pass1/scan):  HKEY@0(8K) HAUX@8K(8K) HISTR@16K(16K) HISTS@32K(16K)
// phase B (pass2, hash live):  SVAL@16K(8K) SIDX@24K(8K) RVAL@32K(4K) RIDX@36K(4K)
// phase C (sort, hash dead):   SSV@0(8K) SSI@8K(8K) RSV@40K(4K) RSI@44K(4K)
#define OFF_HKEY  0
#define OFF_HAUX  8192
#define OFF_HISTR 16384
#define OFF_HISTS 32768
#define OFF_SVAL  16384
#define OFF_SIDX  24576
#define OFF_RVAL  32768
#define OFF_RIDX  36864
#define OFF_SSV   0
#define OFF_SSI   8192
#define OFF_RSV   40960
#define OFF_RSI   45056
#define OFF_MISC  49152
#define SMEM_TOTAL (49152 + 2688)

struct MiscT {
    int   suf[NT];
    float redf[NWARP];
    float redf2[NWARP];
    int   redi[NWARP];
    float m, logS, thresh, lp_samp, t_thr;
    int   Ts, Tr, nsCnt, nrCnt, chunkSel, keepN, sampled, rank_ok;
};

// order-preserving float -> 12-bit bucket
__device__ __forceinline__ int binOf(float f) {
    unsigned u = __float_as_uint(f);
    u = (u & 0x80000000u) ? ~u : (u | 0x80000000u);
    return (int)(u >> 20);
}
__device__ __forceinline__ unsigned f2ord(float f) {
    unsigned u = __float_as_uint(f);
    return (u & 0x80000000u) ? ~u : (u | 0x80000000u);
}
__device__ __forceinline__ float ord2f(unsigned o) {
    unsigned u = (o & 0x80000000u) ? (o & 0x7fffffffu) : ~o;
    return __uint_as_float(u);
}

// JAX threefry2x32 partitionable: key=(0,42), counter=(0, idx), bits=x0^x1
__device__ __forceinline__ float gumbel_at(unsigned idx) {
    const unsigned ks0 = 0u, ks1 = 42u, ks2 = 0x1BD11BDAu ^ 42u;
    unsigned x0 = ks0;
    unsigned x1 = idx + ks1;
#define TF_QR(r) { x0 += x1; x1 = (x1 << (r)) | (x1 >> (32 - (r))); x1 ^= x0; }
    TF_QR(13) TF_QR(15) TF_QR(26) TF_QR(6)   x0 += ks1; x1 += ks2 + 1u;
    TF_QR(17) TF_QR(29) TF_QR(16) TF_QR(24)  x0 += ks2; x1 += ks0 + 2u;
    TF_QR(13) TF_QR(15) TF_QR(26) TF_QR(6)   x0 += ks0; x1 += ks1 + 3u;
    TF_QR(17) TF_QR(29) TF_QR(16) TF_QR(24)  x0 += ks1; x1 += ks2 + 4u;
    TF_QR(13) TF_QR(15) TF_QR(26) TF_QR(6)   x0 += ks2; x1 += ks0 + 5u;
#undef TF_QR
    unsigned bits = x0 ^ x1;
    float f = __uint_as_float((bits >> 9) | 0x3F800000u) - 1.0f;
    float u = fmaxf(f + TINYF, TINYF);
    return -logf(-logf(u));
}

__device__ __forceinline__ unsigned hhash(int v) {
    return (((unsigned)v * 2654435761u) >> 21) & HMASK;
}
__device__ __forceinline__ int hinsert(int* hkey, int v) {
    unsigned h = hhash(v);
    while (true) {
        int k = hkey[h];
        if (k == v) return (int)h;
        if (k == -1) {
            int old = atomicCAS(&hkey[h], -1, v);
            if (old == -1 || old == v) return (int)h;
        }
        h = (h + 1) & HMASK;
    }
}
__device__ __forceinline__ int hfind(const int* hkey, int v) {
    unsigned h = hhash(v);
    while (true) {
        int k = hkey[h];
        if (k == v) return (int)h;
        if (k == -1) return -1;
        h = (h + 1) & HMASK;
    }
}

// penalty adjustment, matching reference fp order
__device__ __forceinline__ float adjv(float lg, int aux, float rp, float fq, float pp) {
    int cnt = aux & 0xFFFF;
    bool outseen = cnt > 0;
    bool seen = outseen || (aux & 0x10000);
    float y = lg;
    if (seen) y = (lg > 0.0f) ? (lg / rp) : (lg * rp);
    y = y - fq * (float)cnt;
    y = y - (outseen ? pp : 0.0f);
    return y;
}

// block argmax: (val desc, idx asc). uniform call.
__device__ void blk_argmax(float v, int idx, MiscT* ms, int tid, float* ov, int* oidx) {
#pragma unroll
    for (int off = 16; off; off >>= 1) {
        float v2 = __shfl_down_sync(0xffffffffu, v, off);
        int   i2 = __shfl_down_sync(0xffffffffu, idx, off);
        if (v2 > v || (v2 == v && i2 < idx)) { v = v2; idx = i2; }
    }
    if ((tid & 31) == 0) { ms->redf[tid >> 5] = v; ms->redi[tid >> 5] = idx; }
    __syncthreads();
    if (tid < 32) {
        v = (tid < NWARP) ? ms->redf[tid] : NEG_INF;
        idx = (tid < NWARP) ? ms->redi[tid] : 0x7fffffff;
#pragma unroll
        for (int off = 16; off; off >>= 1) {
            float v2 = __shfl_down_sync(0xffffffffu, v, off);
            int   i2 = __shfl_down_sync(0xffffffffu, idx, off);
            if (v2 > v || (v2 == v && i2 < idx)) { v = v2; idx = i2; }
        }
        if (tid == 0) { ms->redf[0] = v; ms->redi[0] = idx; }
    }
    __syncthreads();
    *ov = ms->redf[0]; *oidx = ms->redi[0];
    __syncthreads();
}

__device__ int blk_isum(int v, MiscT* ms, int tid) {
#pragma unroll
    for (int off = 16; off; off >>= 1) v += __shfl_down_sync(0xffffffffu, v, off);
    if ((tid & 31) == 0) ms->redi[tid >> 5] = v;
    __syncthreads();
    if (tid < 32) {
        v = (tid < NWARP) ? ms->redi[tid] : 0;
#pragma unroll
        for (int off = 16; off; off >>= 1) v += __shfl_down_sync(0xffffffffu, v, off);
        if (tid == 0) ms->redi[0] = v;
    }
    __syncthreads();
    int r = ms->redi[0];
    __syncthreads();
    return r;
}

// histogram top-tail cutoff: largest bin T with count(bins >= T) >= need
__device__ void cutoff_scan(const int* hist, int need, MiscT* ms, int tid, int* outT) {
    int part = 0;
    int b0 = tid * 8;
#pragma unroll
    for (int b = 0; b < 8; b++) part += hist[b0 + b];
    ms->suf[tid] = part;
    __syncthreads();
    for (int off = 1; off < NT; off <<= 1) {
        int v = (tid + off < NT) ? ms->suf[tid + off] : 0;
        __syncthreads();
        ms->suf[tid] += v;
        __syncthreads();
    }
    if (ms->suf[tid] >= need && (tid == NT - 1 || ms->suf[tid + 1] < need))
        ms->chunkSel = tid;
    __syncthreads();
    if (tid == 0) {
        int c = ms->chunkSel;
        int acc = (c < NT - 1) ? ms->suf[c + 1] : 0;
        int T = c * 8;
        for (int b = c * 8 + 7; b >= c * 8; b--) {
            acc += hist[b];
            if (acc >= need) { T = b; break; }
        }
        *outT = T;
    }
    __syncthreads();
}

__global__ __launch_bounds__(NT, 3)
void sampler_kernel(const float* __restrict__ logits,
                    const float* __restrict__ temperature,
                    const float* __restrict__ top_p,
                    const float* __restrict__ freqp,
                    const float* __restrict__ presp,
                    const float* __restrict__ repp,
                    const int*   __restrict__ topk,
                    const int*   __restrict__ ptoks,
                    const int*   __restrict__ otoks,
                    float*       __restrict__ out) {
    extern __shared__ unsigned char sm[];
    int*   hkey  = (int*)(sm + OFF_HKEY);
    int*   haux  = (int*)(sm + OFF_HAUX);
    int*   histR = (int*)(sm + OFF_HISTR);
    int*   histS = (int*)(sm + OFF_HISTS);
    MiscT* ms    = (MiscT*)(sm + OFF_MISC);

    const int tid = threadIdx.x;
    const int r = blockIdx.x;
    const float* row = logits + (size_t)r * V_;
    const float4* row4 = (const float4*)row;

    const float tr  = temperature[r];
    const float tpv = top_p[r];
    const float fq  = freqp[r];
    const float pp  = presp[r];
    const float rp  = repp[r];
    int k = topk[r];
    if (k < 1) k = 1; if (k > V_) k = V_;
    const float tsafe = (tr < EPS_T) ? 1.0f : tr;

    // ---- init shared ----
    for (int i = tid; i < NBIN; i += NT) histR[i] = 0;
    for (int i = tid; i < HB; i += NT) { hkey[i] = -1; haux[i] = 0; }
    if (tid == 0) { ms->nsCnt = 0; ms->nrCnt = 0; }
    __syncthreads();

    // ---- build penalty hash (dedup + counts) ----
    for (int t = tid; t < O_; t += NT) {
        int v = otoks[r * O_ + t];
        int slot = hinsert(hkey, v);
        atomicAdd(&haux[slot], 1);
    }
    for (int t = tid; t < P_; t += NT) {
        int v = ptoks[r * P_ + t];
        int slot = hinsert(hkey, v);
        atomicOr(&haux[slot], 1 << 16);
    }
    __syncthreads();

    // ---- pass 1: raw histogram + logsumexp (4 independent accumulators) ----
    float ml0 = NEG_INF, ml1 = NEG_INF, ml2 = NEG_INF, ml3 = NEG_INF;
    float sl0 = 0.f, sl1 = 0.f, sl2 = 0.f, sl3 = 0.f;
    for (int i = tid; i < NCH; i += NT) {
        float4 L = row4[i];
        if (L.x > ml0) { sl0 = sl0 * __expf(ml0 - L.x) + 1.0f; ml0 = L.x; }
        else sl0 += __expf(L.x - ml0);
        if (L.y > ml1) { sl1 = sl1 * __expf(ml1 - L.y) + 1.0f; ml1 = L.y; }
        else sl1 += __expf(L.y - ml1);
        if (L.z > ml2) { sl2 = sl2 * __expf(ml2 - L.z) + 1.0f; ml2 = L.z; }
        else sl2 += __expf(L.z - ml2);
        if (L.w > ml3) { sl3 = sl3 * __expf(ml3 - L.w) + 1.0f; ml3 = L.w; }
        else sl3 += __expf(L.w - ml3);
        atomicAdd(&histR[binOf(L.x)], 1);
        atomicAdd(&histR[binOf(L.y)], 1);
        atomicAdd(&histR[binOf(L.z)], 1);
        atomicAdd(&histR[binOf(L.w)], 1);
    }
    // merge 4 accumulators -> (mloc, sloc)
    float mloc = fmaxf(fmaxf(ml0, ml1), fmaxf(ml2, ml3));
    float sloc = 0.0f;
    if (ml0 > NEG_INF) sloc += sl0 * __expf(ml0 - mloc);
    if (ml1 > NEG_INF) sloc += sl1 * __expf(ml1 - mloc);
    if (ml2 > NEG_INF) sloc += sl2 * __expf(ml2 - mloc);
    if (ml3 > NEG_INF) sloc += sl3 * __expf(ml3 - mloc);
    {
#pragma unroll
        for (int off = 16; off; off >>= 1) {
            float m2 = __shfl_down_sync(0xffffffffu, mloc, off);
            float s2 = __shfl_down_sync(0xffffffffu, sloc, off);
            float nm = fmaxf(mloc, m2);
            sloc = sloc * __expf(mloc - nm) + s2 * __expf(m2 - nm);
            mloc = nm;
        }
        if ((tid & 31) == 0) { ms->redf[tid >> 5] = mloc; ms->redf2[tid >> 5] = sloc; }
        __syncthreads();
        if (tid < 32) {
            float mm = (tid < NWARP) ? ms->redf[tid] : NEG_INF;
            float ss = (tid < NWARP) ? ms->redf2[tid] : 0.0f;
#pragma unroll
            for (int off = 16; off; off >>= 1) {
                float m2 = __shfl_down_sync(0xffffffffu, mm, off);
                float s2 = __shfl_down_sync(0xffffffffu, ss, off);
                float nm = fmaxf(mm, m2);
                ss = ss * __expf(mm - nm) + s2 * __expf(m2 - nm);
                mm = nm;
            }
            if (tid == 0) { ms->m = mm; ms->logS = logf(ss); }
        }
        __syncthreads();
    }
    const float m = ms->m, logS = ms->logS;

    // ---- histS = histR + per-flagged-token corrections ----
    for (int i = tid; i < NBIN; i += NT) histS[i] = histR[i];
    __syncthreads();
    for (int s = tid; s < HB; s += NT) {
        int v = hkey[s];
        if (v >= 0) {
            float lg = row[v];
            float x = adjv(lg, haux[s], rp, fq, pp);
            int b1 = binOf(lg), b2 = binOf(x);
            if (b1 != b2) { atomicSub(&histS[b1], 1); atomicAdd(&histS[b2], 1); }
        }
    }
    __syncthreads();

    // ---- cutoffs ----
    cutoff_scan(histS, k, ms, tid, &ms->Ts);
    cutoff_scan(histR, 20, ms, tid, &ms->Tr);
    const int Ts = ms->Ts, Tr = ms->Tr;
    const int Tmin = (Ts < Tr) ? Ts : Tr;
    __syncthreads();   // hist regions free after this

    float* s_val = (float*)(sm + OFF_SVAL);
    int*   s_idx = (int*)(sm + OFF_SIDX);
    float* r_val = (float*)(sm + OFF_RVAL);
    int*   r_idx = (int*)(sm + OFF_RIDX);

    // ---- pass 2: candidate collection (prefilter on raw bin; x <= lg) ----
    for (int i = tid; i < NCH; i += NT) {
        float4 L = row4[i];
        int v0 = 4 * i;
#pragma unroll
        for (int j = 0; j < 4; j++) {
            float lg = (&L.x)[j];
            int b = binOf(lg);
            if (b >= Tmin) {
                int v = v0 + j;
                if (b >= Tr) {
                    int p = atomicAdd(&ms->nrCnt, 1);
                    if (p < RCAP) { r_val[p] = lg; r_idx[p] = v; }
                }
                if (b >= Ts) {
                    float x = lg;
                    int slot = hfind(hkey, v);
                    if (slot >= 0) x = adjv(lg, haux[slot], rp, fq, pp);
                    if (binOf(x) >= Ts) {
                        int p = atomicAdd(&ms->nsCnt, 1);
                        if (p < SCAP) { s_val[p] = x; s_idx[p] = v; }
                    }
                }
            }
        }
    }
    __syncthreads();
    int ns = ms->nsCnt; if (ns > SCAP) ns = SCAP;
    int nr = ms->nrCnt; if (nr > RCAP) nr = RCAP;
    __syncthreads();   // hash free after here

    float* ssort_val = (float*)(sm + OFF_SSV);
    int*   ssort_idx = (int*)(sm + OFF_SSI);
    float* rsort_val = (float*)(sm + OFF_RSV);
    int*   rsort_idx = (int*)(sm + OFF_RSI);

    // ---- rank sort (val desc, token idx asc) ----
    for (int i = tid; i < ns; i += NT) {
        float v = s_val[i]; int id = s_idx[i]; int rk = 0;
        for (int j = 0; j < ns; j++) {
            float w = s_val[j];
            rk += (w > v) || (w == v && s_idx[j] < id);
        }
        ssort_val[rk] = v; ssort_idx[rk] = id;
    }
    for (int i = tid; i < nr; i += NT) {
        float v = r_val[i]; int id = r_idx[i]; int rk = 0;
        for (int j = 0; j < nr; j++) {
            float w = r_val[j];
            rk += (w > v) || (w == v && r_idx[j] < id);
        }
        rsort_val[rk] = v; rsort_idx[rk] = id;
    }
    __syncthreads();

    // ---- top-k / top-p / threshold (thread 0, small N) ----
    if (tid == 0) {
        int kk = (k <= ns) ? k : ns;
        float kth_s = ssort_val[kk - 1] / tsafe;
        int keepN = kk;
        while (keepN < ns && (ssort_val[keepN] / tsafe) >= kth_s) keepN++;
        float s0 = ssort_val[0] / tsafe;
        float S = 0.0f;
        for (int i = 0; i < keepN; i++) S += expf(ssort_val[i] / tsafe - s0);
        float cum = 0.0f; int j = 0;
        for (int i = 0; i < keepN; i++) {
            float p = expf(ssort_val[i] / tsafe - s0) / S;
            if (cum < tpv) j++;
            cum += p;
        }
        if (cum < tpv) j += (V_ - keepN);   // zero-prob tail all keeps
        int nkeep = (j < 1) ? 1 : j;
        float pth = (nkeep <= keepN) ? (ssort_val[nkeep - 1] / tsafe) : NEG_INF;
        ms->thresh = fmaxf(kth_s, pth);
        ms->keepN = keepN;
    }
    __syncthreads();
    const float thresh = ms->thresh;
    const int keepN = ms->keepN;

    // ---- gumbel argmax over surviving candidates ----
    {
        float bv = NEG_INF; int bidx = 0x7fffffff;
        for (int i = tid; i < keepN; i += NT) {
            float s = ssort_val[i] / tsafe;
            if (s >= thresh) {
                float g = gumbel_at((unsigned)(r * V_) + (unsigned)ssort_idx[i]);
                float val = s + g;
                if (val > bv || (val == bv && ssort_idx[i] < bidx)) { bv = val; bidx = ssort_idx[i]; }
            }
        }
        float rv; int ri;
        blk_argmax(bv, bidx, ms, tid, &rv, &ri);
        if (tid == 0) {
            // greedy = first-index argmax of adjusted x = ssort_idx[0]
            int sampled = (tr < EPS_T) ? ssort_idx[0] : ri;
            ms->sampled = sampled;
            float lgs = row[sampled];
            float c = (lgs - m) - logS;
            ms->lp_samp = c;
            // invert monotone f(y)=(y-m)-logS: min ordered-float t with f(t) >= c
            unsigned lo = 0u, hi = f2ord(lgs);
            while (lo < hi) {
                unsigned mid = lo + ((hi - lo) >> 1);
                float y = ord2f(mid);
                if (((y - m) - logS) >= c) hi = mid; else lo = mid + 1;
            }
            float t = ord2f(hi);
            ms->t_thr = t;
            ms->rank_ok = (binOf(t) >= Tr) && (ms->nrCnt <= RCAP);
        }
        __syncthreads();
    }
    const int sampled = ms->sampled;
    const float lp_samp = ms->lp_samp;
    const float t_thr = ms->t_thr;
    const int rank_ok = ms->rank_ok;

    // ---- outputs (except rank) ----
    if (tid < 20) {
        out[IDX_OFF + r * 21 + tid] = (float)rsort_idx[tid];
        out[LP_OFF  + r * 21 + tid] = (rsort_val[tid] - m) - logS;
    }
    if (tid == 0) {
        out[r] = (float)sampled;
        out[IDX_OFF + r * 21 + 20] = (float)sampled;
        out[LP_OFF  + r * 21 + 20] = lp_samp;
    }

    // ---- rank: count lg >= t  (candidates cover all such elements if rank_ok) ----
    int cnt = 0;
    if (rank_ok) {
        for (int i = tid; i < nr; i += NT) cnt += (rsort_val[i] >= t_thr) ? 1 : 0;
    } else {
        for (int i = tid; i < NCH; i += NT) {
            float4 L = row4[i];
            cnt += (L.x >= t_thr) + (L.y >= t_thr) + (L.z >= t_thr) + (L.w >= t_thr);
        }
    }
    int total = blk_isum(cnt, ms, tid);
    if (tid == 0) out[RK_OFF + r] = (float)total;
}

extern "C" void kernel_launch(void* const* d_in, const int* in_sizes, int n_in,
                              void* d_out, int out_size) {
    const float* logits = (const float*)d_in[0];
    const float* temperature = (const float*)d_in[1];
    const float* topp = (const float*)d_in[2];
    const float* freqp = (const float*)d_in[3];
    const float* presp = (const float*)d_in[4];
    const float* repp = (const float*)d_in[5];
    const int* topk = (const int*)d_in[6];
    const int* ptoks = (const int*)d_in[7];
    const int* otoks = (const int*)d_in[8];
    float* out = (float*)d_out;

    cudaFuncSetAttribute(sampler_kernel,
                         cudaFuncAttributeMaxDynamicSharedMemorySize, SMEM_TOTAL);
    sampler_kernel<<<B_, NT, SMEM_TOTAL>>>(logits, temperature, topp, freqp,
                                           presp, repp, topk, ptoks, otoks, out);
}

// round 8
// speedup vs baseline: 1.3171x; 1.0040x over previous
#include <cuda_runtime.h>

#define B_    256
#define V_    128000
#define P_    512
#define O_    128
#define NT    512
#define NWARP 16
#define QS    4
#define VQ    (V_/QS)      // 32000
#define CQ    (VQ/4)       // 8000 float4 per quarter
#define HB    2048
#define HMASK (HB-1)
#define NBIN  4096
#define SCAP  2048
#define RCAP  2048
#define NEG_INF (__int_as_float(0xff800000))
#define TINYF 1.1754943508222875e-38f
#define EPS_T 1e-5f

// output layout (floats): [sampled B][idx B*21][lp B*21][ranks B]
#define IDX_OFF 256
#define LP_OFF  5632
#define RK_OFF  11008

// ---------------- global scratch (static __device__, allowed) ----------------
__device__ int   g_histR[B_][NBIN];
__device__ int   g_histC[B_][NBIN];
__device__ float g_expsum[B_][QS];
__device__ int   g_Ts[B_];
__device__ int   g_Trc[B_];
__device__ float g_lse[B_];
__device__ float g_sval[B_][SCAP];
__device__ int   g_sidx[B_][SCAP];
__device__ float g_rval[B_][RCAP];
__device__ int   g_ridx[B_][RCAP];
__device__ int   g_ns[B_];
__device__ int   g_nr[B_];

// ---------------- helpers ----------------
__device__ __forceinline__ int binOf(float f) {
    unsigned u = __float_as_uint(f);
    u = (u & 0x80000000u) ? ~u : (u | 0x80000000u);
    return (int)(u >> 20);
}
__device__ __forceinline__ unsigned f2ord(float f) {
    unsigned u = __float_as_uint(f);
    return (u & 0x80000000u) ? ~u : (u | 0x80000000u);
}
__device__ __forceinline__ float ord2f(unsigned o) {
    unsigned u = (o & 0x80000000u) ? (o & 0x7fffffffu) : ~o;
    return __uint_as_float(u);
}

// JAX threefry2x32 partitionable: key=(0,42), counter=(0, idx), bits=x0^x1
__device__ __forceinline__ float gumbel_at(unsigned idx) {
    const unsigned ks0 = 0u, ks1 = 42u, ks2 = 0x1BD11BDAu ^ 42u;
    unsigned x0 = ks0;
    unsigned x1 = idx + ks1;
#define TF_QR(r) { x0 += x1; x1 = (x1 << (r)) | (x1 >> (32 - (r))); x1 ^= x0; }
    TF_QR(13) TF_QR(15) TF_QR(26) TF_QR(6)   x0 += ks1; x1 += ks2 + 1u;
    TF_QR(17) TF_QR(29) TF_QR(16) TF_QR(24)  x0 += ks2; x1 += ks0 + 2u;
    TF_QR(13) TF_QR(15) TF_QR(26) TF_QR(6)   x0 += ks0; x1 += ks1 + 3u;
    TF_QR(17) TF_QR(29) TF_QR(16) TF_QR(24)  x0 += ks1; x1 += ks2 + 4u;
    TF_QR(13) TF_QR(15) TF_QR(26) TF_QR(6)   x0 += ks2; x1 += ks0 + 5u;
#undef TF_QR
    unsigned bits = x0 ^ x1;
    float f = __uint_as_float((bits >> 9) | 0x3F800000u) - 1.0f;
    float u = fmaxf(f + TINYF, TINYF);
    return -logf(-logf(u));
}

__device__ __forceinline__ unsigned hhash(int v) {
    return (((unsigned)v * 2654435761u) >> 21) & HMASK;
}
__device__ __forceinline__ int hinsert(int* hkey, int v) {
    unsigned h = hhash(v);
    while (true) {
        int k = hkey[h];
        if (k == v) return (int)h;
        if (k == -1) {
            int old = atomicCAS(&hkey[h], -1, v);
            if (old == -1 || old == v) return (int)h;
        }
        h = (h + 1) & HMASK;
    }
}
__device__ __forceinline__ int hfind(const int* hkey, int v) {
    unsigned h = hhash(v);
    while (true) {
        int k = hkey[h];
        if (k == v) return (int)h;
        if (k == -1) return -1;
        h = (h + 1) & HMASK;
    }
}

// penalty adjustment, matching reference fp order (x <= lg always)
__device__ __forceinline__ float adjv(float lg, int aux, float rp, float fq, float pp) {
    int cnt = aux & 0xFFFF;
    bool outseen = cnt > 0;
    bool seen = outseen || (aux & 0x10000);
    float y = lg;
    if (seen) y = (lg > 0.0f) ? (lg / rp) : (lg * rp);
    y = y - fq * (float)cnt;
    y = y - (outseen ? pp : 0.0f);
    return y;
}

// block argmax (val desc, idx asc)
__device__ void blk_argmax(float v, int idx, float* redf, int* redi, int tid,
                           float* ov, int* oidx) {
#pragma unroll
    for (int off = 16; off; off >>= 1) {
        float v2 = __shfl_down_sync(0xffffffffu, v, off);
        int   i2 = __shfl_down_sync(0xffffffffu, idx, off);
        if (v2 > v || (v2 == v && i2 < idx)) { v = v2; idx = i2; }
    }
    if ((tid & 31) == 0) { redf[tid >> 5] = v; redi[tid >> 5] = idx; }
    __syncthreads();
    if (tid < 32) {
        v = (tid < NWARP) ? redf[tid] : NEG_INF;
        idx = (tid < NWARP) ? redi[tid] : 0x7fffffff;
#pragma unroll
        for (int off = 16; off; off >>= 1) {
            float v2 = __shfl_down_sync(0xffffffffu, v, off);
            int   i2 = __shfl_down_sync(0xffffffffu, idx, off);
            if (v2 > v || (v2 == v && i2 < idx)) { v = v2; idx = i2; }
        }
        if (tid == 0) { redf[0] = v; redi[0] = idx; }
    }
    __syncthreads();
    *ov = redf[0]; *oidx = redi[0];
    __syncthreads();
}

__device__ int blk_isum(int v, int* redi, int tid) {
#pragma unroll
    for (int off = 16; off; off >>= 1) v += __shfl_down_sync(0xffffffffu, v, off);
    if ((tid & 31) == 0) redi[tid >> 5] = v;
    __syncthreads();
    if (tid < 32) {
        v = (tid < NWARP) ? redi[tid] : 0;
#pragma unroll
        for (int off = 16; off; off >>= 1) v += __shfl_down_sync(0xffffffffu, v, off);
        if (tid == 0) redi[0] = v;
    }
    __syncthreads();
    int r = redi[0];
    __syncthreads();
    return r;
}

// ---------------- K0: zero scratch ----------------
__global__ void k0_zero() {
    int idx = blockIdx.x * blockDim.x + threadIdx.x;
    int stride = gridDim.x * blockDim.x;
    int total = B_ * NBIN;
    for (int i = idx; i < total; i += stride) {
        ((int*)g_histR)[i] = 0;
        ((int*)g_histC)[i] = 0;
    }
    if (idx < B_) { g_ns[idx] = 0; g_nr[idx] = 0; }
}

// ---------------- K1: histogram + exp-sum (4 CTAs/row) ----------------
__global__ __launch_bounds__(NT) void k1_hist(
    const float* __restrict__ logits,
    const float* __restrict__ freqp, const float* __restrict__ presp,
    const float* __restrict__ repp,
    const int* __restrict__ ptoks, const int* __restrict__ otoks)
{
    __shared__ int hkey[HB];
    __shared__ int haux[HB];
    __shared__ int shist[NBIN];
    __shared__ float redf[NWARP];

    const int tid = threadIdx.x;
    const int r = blockIdx.x / QS;
    const int q = blockIdx.x % QS;
    const float* row = logits + (size_t)r * V_;

    for (int i = tid; i < NBIN; i += NT) shist[i] = 0;
    for (int i = tid; i < HB; i += NT) { hkey[i] = -1; haux[i] = 0; }
    __syncthreads();

    for (int t = tid; t < O_; t += NT)
        atomicAdd(&haux[hinsert(hkey, otoks[r * O_ + t])], 1);
    for (int t = tid; t < P_; t += NT)
        atomicOr(&haux[hinsert(hkey, ptoks[r * P_ + t])], 1 << 16);
    __syncthreads();

    const float4* q4 = (const float4*)(row + q * VQ);
    float s0 = 0.f, s1 = 0.f, s2 = 0.f, s3 = 0.f;
#pragma unroll 2
    for (int i = tid; i < CQ; i += NT) {
        float4 L = q4[i];
        s0 += __expf(L.x); s1 += __expf(L.y);
        s2 += __expf(L.z); s3 += __expf(L.w);
        atomicAdd(&shist[binOf(L.x)], 1);
        atomicAdd(&shist[binOf(L.y)], 1);
        atomicAdd(&shist[binOf(L.z)], 1);
        atomicAdd(&shist[binOf(L.w)], 1);
    }
    float sv = (s0 + s1) + (s2 + s3);
#pragma unroll
    for (int off = 16; off; off >>= 1) sv += __shfl_down_sync(0xffffffffu, sv, off);
    if ((tid & 31) == 0) redf[tid >> 5] = sv;
    __syncthreads();
    if (tid < 32) {
        float v = (tid < NWARP) ? redf[tid] : 0.f;
#pragma unroll
        for (int off = 16; off; off >>= 1) v += __shfl_down_sync(0xffffffffu, v, off);
        if (tid == 0) g_expsum[r][q] = v;
    }

    // corrections for flagged tokens in this quarter (sparse, onto g_histC)
    const float fq = freqp[r], pp = presp[r], rp = repp[r];
    const int lo = q * VQ, hi = lo + VQ;
    for (int s = tid; s < HB; s += NT) {
        int v = hkey[s];
        if (v >= lo && v < hi) {
            float lg = row[v];
            float x = adjv(lg, haux[s], rp, fq, pp);
            int b1 = binOf(lg), b2 = binOf(x);
            if (b1 != b2) {
                atomicSub(&g_histC[r][b1], 1);
                atomicAdd(&g_histC[r][b2], 1);
            }
        }
    }
    __syncthreads();
    // flush nonzero bins to global
    for (int b = tid; b < NBIN; b += NT) {
        int c = shist[b];
        if (c) atomicAdd(&g_histR[r][b], c);
    }
}

// ---------------- K2: cutoffs + lse ----------------
__device__ int cutoff_g(const int* __restrict__ hR, const int* __restrict__ hC,
                        int need, int* suf, int* selp, int* outp, int tid) {
    int part = 0;
    int b0 = tid * 8;
#pragma unroll
    for (int b = 0; b < 8; b++) {
        int c = hR[b0 + b];
        if (hC) c += hC[b0 + b];
        part += c;
    }
    suf[tid] = part;
    __syncthreads();
    for (int off = 1; off < NT; off <<= 1) {
        int v = (tid + off < NT) ? suf[tid + off] : 0;
        __syncthreads();
        suf[tid] += v;
        __syncthreads();
    }
    if (suf[tid] >= need && (tid == NT - 1 || suf[tid + 1] < need)) *selp = tid;
    __syncthreads();
    if (tid == 0) {
        int c = *selp;
        int acc = (c < NT - 1) ? suf[c + 1] : 0;
        int T = c * 8;
        for (int b = c * 8 + 7; b >= c * 8; b--) {
            int cc = hR[b];
            if (hC) cc += hC[b];
            acc += cc;
            if (acc >= need) { T = b; break; }
        }
        *outp = T;
    }
    __syncthreads();
    int T = *outp;
    __syncthreads();
    return T;
}

__global__ __launch_bounds__(NT) void k2_cutoff(const int* __restrict__ topk) {
    __shared__ int suf[NT];
    __shared__ int selp;
    __shared__ int outp;
    const int tid = threadIdx.x, r = blockIdx.x;
    int k = topk[r];
    if (k < 1) k = 1; if (k > V_) k = V_;
    int Ts = cutoff_g(g_histR[r], g_histC[r], k, suf, &selp, &outp, tid);
    int Tr = cutoff_g(g_histR[r], 0, 20, suf, &selp, &outp, tid);
    if (tid == 0) {
        g_Ts[r] = Ts;
        g_Trc[r] = (Tr < Ts) ? Tr : Ts;
        float s = (g_expsum[r][0] + g_expsum[r][1]) + (g_expsum[r][2] + g_expsum[r][3]);
        g_lse[r] = logf(s);
    }
}

// ---------------- K3: candidate collection (4 CTAs/row) ----------------
__global__ __launch_bounds__(NT) void k3_collect(
    const float* __restrict__ logits,
    const float* __restrict__ freqp, const float* __restrict__ presp,
    const float* __restrict__ repp,
    const int* __restrict__ ptoks, const int* __restrict__ otoks)
{
    __shared__ int hkey[HB];
    __shared__ int haux[HB];
    const int tid = threadIdx.x;
    const int r = blockIdx.x / QS;
    const int q = blockIdx.x % QS;
    const float* row = logits + (size_t)r * V_;

    for (int i = tid; i < HB; i += NT) { hkey[i] = -1; haux[i] = 0; }
    __syncthreads();
    for (int t = tid; t < O_; t += NT)
        atomicAdd(&haux[hinsert(hkey, otoks[r * O_ + t])], 1);
    for (int t = tid; t < P_; t += NT)
        atomicOr(&haux[hinsert(hkey, ptoks[r * P_ + t])], 1 << 16);
    __syncthreads();

    const float fq = freqp[r], pp = presp[r], rp = repp[r];
    const int Ts = g_Ts[r], Tc = g_Trc[r];   // Tc <= Ts
    const float4* q4 = (const float4*)(row + q * VQ);
    const int base = q * VQ;
#pragma unroll 2
    for (int i = tid; i < CQ; i += NT) {
        float4 L = q4[i];
        int v0 = base + 4 * i;
#pragma unroll
        for (int j = 0; j < 4; j++) {
            float lg = (&L.x)[j];
            int b = binOf(lg);
            if (b >= Tc) {
                int v = v0 + j;
                int p = atomicAdd(&g_nr[r], 1);
                if (p < RCAP) { g_rval[r][p] = lg; g_ridx[r][p] = v; }
                if (b >= Ts) {
                    float x = lg;
                    int slot = hfind(hkey, v);
                    if (slot >= 0) x = adjv(lg, haux[slot], rp, fq, pp);
                    if (binOf(x) >= Ts) {
                        int ps = atomicAdd(&g_ns[r], 1);
                        if (ps < SCAP) { g_sval[r][ps] = x; g_sidx[r][ps] = v; }
                    }
                }
            }
        }
    }
}

// ---------------- K4: selection + sampling + outputs ----------------
struct M4 {
    float redf[NWARP];
    int   redi[NWARP];
    float thresh, lp_samp, t_thr;
    int   keepN, sampled, rank_ok;
};
#define K4_SMEM (65536 + (int)sizeof(M4))

__global__ __launch_bounds__(NT) void k4_final(
    const float* __restrict__ logits,
    const float* __restrict__ temperature, const float* __restrict__ top_p,
    const int* __restrict__ topk, float* __restrict__ out)
{
    extern __shared__ unsigned char sm[];
    float* s_val = (float*)(sm);
    int*   s_idx = (int*)(sm + 8192);
    float* r_val = (float*)(sm + 16384);
    int*   r_idx = (int*)(sm + 24576);
    float* ssv   = (float*)(sm + 32768);
    int*   ssi   = (int*)(sm + 40960);
    float* rsv   = (float*)(sm + 49152);
    int*   rsi   = (int*)(sm + 57344);
    M4*    ms    = (M4*)(sm + 65536);

    const int tid = threadIdx.x, r = blockIdx.x;
    const float* row = logits + (size_t)r * V_;
    const float lse = g_lse[r];
    const float tr = temperature[r], tpv = top_p[r];
    int k = topk[r];
    if (k < 1) k = 1; if (k > V_) k = V_;
    const float tsafe = (tr < EPS_T) ? 1.0f : tr;

    const int nsFull = g_ns[r], nrFull = g_nr[r];
    int ns = (nsFull < SCAP) ? nsFull : SCAP;
    int nr = (nrFull < RCAP) ? nrFull : RCAP;
    for (int i = tid; i < ns; i += NT) { s_val[i] = g_sval[r][i]; s_idx[i] = g_sidx[r][i]; }
    for (int i = tid; i < nr; i += NT) { r_val[i] = g_rval[r][i]; r_idx[i] = g_ridx[r][i]; }
    __syncthreads();

    // rank-sort both lists (val desc, token idx asc) -> canonical order
    for (int i = tid; i < ns; i += NT) {
        float v = s_val[i]; int id = s_idx[i]; int rk = 0;
        for (int j = 0; j < ns; j++) {
            float w = s_val[j];
            rk += (w > v) || (w == v && s_idx[j] < id);
        }
        ssv[rk] = v; ssi[rk] = id;
    }
    for (int i = tid; i < nr; i += NT) {
        float v = r_val[i]; int id = r_idx[i]; int rk = 0;
        for (int j = 0; j < nr; j++) {
            float w = r_val[j];
            rk += (w > v) || (w == v && r_idx[j] < id);
        }
        rsv[rk] = v; rsi[rk] = id;
    }
    __syncthreads();

    // top-k / top-p threshold (thread 0, small N)
    if (tid == 0) {
        int kk = (k <= ns) ? k : ns;
        float kth_s = ssv[kk - 1] / tsafe;
        int keepN = kk;
        while (keepN < ns && (ssv[keepN] / tsafe) >= kth_s) keepN++;
        float s0 = ssv[0] / tsafe;
        float S = 0.0f;
        for (int i = 0; i < keepN; i++) S += expf(ssv[i] / tsafe - s0);
        float cum = 0.0f; int j = 0;
        for (int i = 0; i < keepN; i++) {
            float p = expf(ssv[i] / tsafe - s0) / S;
            if (cum < tpv) j++;
            cum += p;
        }
        if (cum < tpv) j += (V_ - keepN);   // zero-prob tail all keeps
        int nkeep = (j < 1) ? 1 : j;
        float pth = (nkeep <= keepN) ? (ssv[nkeep - 1] / tsafe) : NEG_INF;
        ms->thresh = fmaxf(kth_s, pth);
        ms->keepN = keepN;
    }
    __syncthreads();
    const float thresh = ms->thresh;
    const int keepN = ms->keepN;

    // gumbel argmax over surviving candidates
    {
        float bv = NEG_INF; int bidx = 0x7fffffff;
        for (int i = tid; i < keepN; i += NT) {
            float s = ssv[i] / tsafe;
            if (s >= thresh) {
                float g = gumbel_at((unsigned)(r * V_) + (unsigned)ssi[i]);
                float val = s + g;
                if (val > bv || (val == bv && ssi[i] < bidx)) { bv = val; bidx = ssi[i]; }
            }
        }
        float rv; int ri;
        blk_argmax(bv, bidx, ms->redf, ms->redi, tid, &rv, &ri);
        if (tid == 0) {
            int sampled = (tr < EPS_T) ? ssi[0] : ri;   // greedy = first-index argmax
            ms->sampled = sampled;
            float lgs = row[sampled];
            float c = lgs - lse;
            ms->lp_samp = c;
            // invert monotone f(y) = y - lse: min ordered-float t with f(t) >= c
            unsigned lo = 0u, hi = f2ord(lgs);
            while (lo < hi) {
                unsigned mid = lo + ((hi - lo) >> 1);
                float y = ord2f(mid);
                if ((y - lse) >= c) hi = mid; else lo = mid + 1;
            }
            float t = ord2f(hi);
            ms->t_thr = t;
            ms->rank_ok = (binOf(t) >= g_Trc[r]) && (nrFull <= RCAP);
        }
        __syncthreads();
    }
    const int sampled = ms->sampled;
    const float lp_samp = ms->lp_samp;
    const float t_thr = ms->t_thr;
    const int rank_ok = ms->rank_ok;

    // outputs (except rank)
    if (tid < 20) {
        out[IDX_OFF + r * 21 + tid] = (float)rsi[tid];
        out[LP_OFF  + r * 21 + tid] = rsv[tid] - lse;
    }
    if (tid == 0) {
        out[r] = (float)sampled;
        out[IDX_OFF + r * 21 + 20] = (float)sampled;
        out[LP_OFF  + r * 21 + 20] = lp_samp;
    }

    // rank: count lg >= t_thr
    int cnt = 0;
    if (rank_ok) {
        for (int i = tid; i < nr; i += NT) cnt += (rsv[i] >= t_thr) ? 1 : 0;
    } else {
        const float4* row4 = (const float4*)row;
        for (int i = tid; i < V_ / 4; i += NT) {
            float4 L = row4[i];
            cnt += (L.x >= t_thr) + (L.y >= t_thr) + (L.z >= t_thr) + (L.w >= t_thr);
        }
    }
    int total = blk_isum(cnt, ms->redi, tid);
    if (tid == 0) out[RK_OFF + r] = (float)total;
}

// ---------------- launch ----------------
extern "C" void kernel_launch(void* const* d_in, const int* in_sizes, int n_in,
                              void* d_out, int out_size) {
    const float* logits = (const float*)d_in[0];
    const float* temperature = (const float*)d_in[1];
    const float* topp = (const float*)d_in[2];
    const float* freqp = (const float*)d_in[3];
    const float* presp = (const float*)d_in[4];
    const float* repp = (const float*)d_in[5];
    const int* topk = (const int*)d_in[6];
    const int* ptoks = (const int*)d_in[7];
    const int* otoks = (const int*)d_in[8];
    float* out = (float*)d_out;

    cudaFuncSetAttribute(k4_final,
                         cudaFuncAttributeMaxDynamicSharedMemorySize, K4_SMEM);

    k0_zero<<<512, 256>>>();
    k1_hist<<<B_ * QS, NT>>>(logits, freqp, presp, repp, ptoks, otoks);
    k2_cutoff<<<B_, NT>>>(topk);
    k3_collect<<<B_ * QS, NT>>>(logits, freqp, presp, repp, ptoks, otoks);
    k4_final<<<B_, NT, K4_SMEM>>>(logits, temperature, topp, topk, out);
}